// round 6
// baseline (speedup 1.0000x reference)
#include <cuda_runtime.h>

#define NN   100000
#define EE   1600000
#define EAA  1000000
#define GG   512
#define F_INN 16
#define HH   32

#define SCAN_B 1024
#define SCAN_GRID ((NN + SCAN_B - 1) / SCAN_B)

// ---- scratch (device globals) ----
__device__ __align__(16) float g_deg[NN];          // dinv
__device__ __align__(16) float g_y  [NN * HH];     // layer-1 gather source (y1)
__device__ __align__(16) float g_y2 [NN * HH];     // layer-2 gather source (y2)
__device__ __align__(16) float g_h  [NN * HH];     // layer-2 output (edge head)
__device__ __align__(16) float g_u  [NN * HH];     // h @ Wbil
__device__ __align__(16) float g_pooled[GG * HH];
__device__ float g_cnt[GG];
__device__ int   g_cnt_i[NN];                      // in-degree (no self loop)
__device__ int   g_pos[NN];                        // CSR row start (stable)
__device__ int   g_cur[NN];                        // absolute cursor -> row end after fill
__device__ int   g_csr[EE];                        // src ids grouped by dst
__device__ int   g_total;

// ---------------- build kernels ----------------

__global__ void k_zero() {
    int i = blockIdx.x * blockDim.x + threadIdx.x;
    if (i < NN)      g_cnt_i[i] = 0;
    if (i < GG * HH) g_pooled[i] = 0.f;
    if (i < GG)      g_cnt[i] = 0.f;
    if (i == 0)      g_total = 0;
}

// 4 edges per thread (int4), independent atomics for MLP
__global__ void k_count(const int* __restrict__ dst) {
    int t = blockIdx.x * blockDim.x + threadIdx.x;
    int e = t * 4;
    if (e + 3 < EE) {
        int4 d = reinterpret_cast<const int4*>(dst)[t];
        atomicAdd(&g_cnt_i[d.x], 1);
        atomicAdd(&g_cnt_i[d.y], 1);
        atomicAdd(&g_cnt_i[d.z], 1);
        atomicAdd(&g_cnt_i[d.w], 1);
    } else {
        for (int k = e; k < EE; k++) atomicAdd(&g_cnt_i[dst[k]], 1);
    }
}

// blockwise exclusive scan; block base via one atomicAdd per block.
// writes g_pos AND g_cur (= same start value); computes dinv.
__global__ void k_scan() {
    __shared__ int s[SCAN_B];
    __shared__ int base;
    int tid = threadIdx.x;
    int i = blockIdx.x * SCAN_B + tid;
    int v = (i < NN) ? g_cnt_i[i] : 0;
    s[tid] = v;
    __syncthreads();
#pragma unroll
    for (int off = 1; off < SCAN_B; off <<= 1) {
        int t = (tid >= off) ? s[tid - off] : 0;
        __syncthreads();
        s[tid] += t;
        __syncthreads();
    }
    if (tid == 0) base = atomicAdd(&g_total, s[SCAN_B - 1]);
    __syncthreads();
    if (i < NN) {
        int p = base + s[tid] - v;             // exclusive
        g_pos[i] = p;
        g_cur[i] = p;
        g_deg[i] = rsqrtf((float)v + 1.0f);    // dinv incl self-loop
    }
}

// 4 edges per thread; absolute slot straight from the cursor (no g_pos read)
__global__ void k_fill(const int* __restrict__ src, const int* __restrict__ dst) {
    int t = blockIdx.x * blockDim.x + threadIdx.x;
    int e = t * 4;
    if (e + 3 < EE) {
        int4 d = reinterpret_cast<const int4*>(dst)[t];
        int4 sv = reinterpret_cast<const int4*>(src)[t];
        int s0 = atomicAdd(&g_cur[d.x], 1);
        int s1 = atomicAdd(&g_cur[d.y], 1);
        int s2 = atomicAdd(&g_cur[d.z], 1);
        int s3 = atomicAdd(&g_cur[d.w], 1);
        g_csr[s0] = sv.x;
        g_csr[s1] = sv.y;
        g_csr[s2] = sv.z;
        g_csr[s3] = sv.w;
    } else {
        for (int k = e; k < EE; k++) {
            int slot = atomicAdd(&g_cur[dst[k]], 1);
            g_csr[slot] = src[k];
        }
    }
}

// ---------------- compute kernels ----------------

// y1 = (x @ W1) * dinv ; 4 threads per node
__global__ void k_mm1(const float* __restrict__ x, const float* __restrict__ W1) {
    __shared__ float sW[F_INN * HH];
    for (int i = threadIdx.x; i < F_INN * HH; i += blockDim.x) sW[i] = W1[i];
    __syncthreads();
    int t = blockIdx.x * blockDim.x + threadIdx.x;
    int node = t >> 2, q = t & 3;
    if (node >= NN) return;
    float acc[8];
#pragma unroll
    for (int j = 0; j < 8; j++) acc[j] = 0.f;
    const float4* xr = reinterpret_cast<const float4*>(x + node * F_INN);
#pragma unroll
    for (int kk = 0; kk < F_INN / 4; kk++) {
        float4 xv = xr[kk];
        float xs[4] = {xv.x, xv.y, xv.z, xv.w};
#pragma unroll
        for (int p = 0; p < 4; p++) {
            int k = kk * 4 + p;
#pragma unroll
            for (int j = 0; j < 8; j++)
                acc[j] = fmaf(xs[p], sW[k * HH + q * 8 + j], acc[j]);
        }
    }
    float dv = g_deg[node];
    int o = node * 8 + q * 2;
    reinterpret_cast<float4*>(g_y)[o]     = make_float4(acc[0]*dv, acc[1]*dv, acc[2]*dv, acc[3]*dv);
    reinterpret_cast<float4*>(g_y)[o + 1] = make_float4(acc[4]*dv, acc[5]*dv, acc[6]*dv, acc[7]*dv);
}

// gather helper: sum y4 rows listed in g_csr[base..base+m) at chunk c, unroll 4
__device__ __forceinline__ float4 gather_rows(const float4* __restrict__ y4,
                                              int base, int m, int c, float4 acc) {
    float4 acc2 = make_float4(0.f, 0.f, 0.f, 0.f);
    int i = 0;
    for (; i + 4 <= m; i += 4) {
        int s0 = g_csr[base + i];
        int s1 = g_csr[base + i + 1];
        int s2 = g_csr[base + i + 2];
        int s3 = g_csr[base + i + 3];
        float4 v0 = y4[s0 * 8 + c];
        float4 v1 = y4[s1 * 8 + c];
        float4 v2 = y4[s2 * 8 + c];
        float4 v3 = y4[s3 * 8 + c];
        acc.x  += v0.x + v1.x; acc.y  += v0.y + v1.y;
        acc.z  += v0.z + v1.z; acc.w  += v0.w + v1.w;
        acc2.x += v2.x + v3.x; acc2.y += v2.y + v3.y;
        acc2.z += v2.z + v3.z; acc2.w += v2.w + v3.w;
    }
    for (; i < m; i++) {
        float4 v = y4[g_csr[base + i] * 8 + c];
        acc.x += v.x; acc.y += v.y; acc.z += v.z; acc.w += v.w;
    }
    acc.x += acc2.x; acc.y += acc2.y; acc.z += acc2.z; acc.w += acc2.w;
    return acc;
}

// fused: CSR gather of y1 + relu epilogue (smem) + @W2 matmul -> y2 (*dinv)
#define NODES_PER_BLK 32
#define HPAD 36
__global__ void k_gmm(const float* __restrict__ b1, const float* __restrict__ W2) {
    __shared__ float sW[HH * HH];
    __shared__ float sb[HH];
    __shared__ float sh[NODES_PER_BLK * HPAD];
    for (int i = threadIdx.x; i < HH * HH; i += blockDim.x) sW[i] = W2[i];
    if (threadIdx.x < HH) sb[threadIdx.x] = b1[threadIdx.x];
    __syncthreads();

    int tid = threadIdx.x;
    int nl = tid >> 3, c = tid & 7;
    int node = blockIdx.x * NODES_PER_BLK + nl;
    bool ok = node < NN;

    if (ok) {
        int base = g_pos[node];
        int m    = g_cur[node] - base;
        const float4* y4 = reinterpret_cast<const float4*>(g_y);
        float4 acc = gather_rows(y4, base, m, c, y4[node * 8 + c]);
        float dv = g_deg[node];
        float* hr = sh + nl * HPAD + c * 4;
        hr[0] = fmaxf(acc.x * dv + sb[c*4+0], 0.f);
        hr[1] = fmaxf(acc.y * dv + sb[c*4+1], 0.f);
        hr[2] = fmaxf(acc.z * dv + sb[c*4+2], 0.f);
        hr[3] = fmaxf(acc.w * dv + sb[c*4+3], 0.f);
    }
    __syncthreads();
    if (!ok) return;

    float a0 = 0.f, a1 = 0.f, a2 = 0.f, a3 = 0.f;
    const float* hrow = sh + nl * HPAD;
#pragma unroll
    for (int k = 0; k < HH; k++) {
        float hv = hrow[k];
        a0 = fmaf(hv, sW[k * HH + c * 4 + 0], a0);
        a1 = fmaf(hv, sW[k * HH + c * 4 + 1], a1);
        a2 = fmaf(hv, sW[k * HH + c * 4 + 2], a2);
        a3 = fmaf(hv, sW[k * HH + c * 4 + 3], a3);
    }
    float dv = g_deg[node];
    reinterpret_cast<float4*>(g_y2)[node * 8 + c] =
        make_float4(a0 * dv, a1 * dv, a2 * dv, a3 * dv);
}

// fused: CSR gather of y2 + epilogue -> g_h, pooling, u = h2 @ Wbil -> g_u
__global__ void k_ghead(const float* __restrict__ b2, const float* __restrict__ Wbil,
                        const int* __restrict__ batch) {
    __shared__ float sW[HH * HH];
    __shared__ float sb[HH];
    __shared__ float sh[NODES_PER_BLK * HPAD];
    for (int i = threadIdx.x; i < HH * HH; i += blockDim.x) sW[i] = Wbil[i];
    if (threadIdx.x < HH) sb[threadIdx.x] = b2[threadIdx.x];
    __syncthreads();

    int tid = threadIdx.x;
    int nl = tid >> 3, c = tid & 7;
    int node = blockIdx.x * NODES_PER_BLK + nl;
    bool ok = node < NN;

    if (ok) {
        int base = g_pos[node];
        int m    = g_cur[node] - base;
        const float4* y4 = reinterpret_cast<const float4*>(g_y2);
        float4 acc = gather_rows(y4, base, m, c, y4[node * 8 + c]);
        float dv = g_deg[node];
        float4 h2;
        h2.x = acc.x * dv + sb[c*4+0];
        h2.y = acc.y * dv + sb[c*4+1];
        h2.z = acc.z * dv + sb[c*4+2];
        h2.w = acc.w * dv + sb[c*4+3];
        float* hr = sh + nl * HPAD + c * 4;
        hr[0] = h2.x; hr[1] = h2.y; hr[2] = h2.z; hr[3] = h2.w;
        reinterpret_cast<float4*>(g_h)[node * 8 + c] = h2;
        int g = batch[node];
        atomicAdd(reinterpret_cast<float4*>(g_pooled) + g * 8 + c, h2);
        if (c == 0) atomicAdd(&g_cnt[g], 1.0f);
    }
    __syncthreads();
    if (!ok) return;

    float a0 = 0.f, a1 = 0.f, a2 = 0.f, a3 = 0.f;
    const float* hrow = sh + nl * HPAD;
#pragma unroll
    for (int k = 0; k < HH; k++) {
        float hv = hrow[k];
        a0 = fmaf(hv, sW[k * HH + c * 4 + 0], a0);
        a1 = fmaf(hv, sW[k * HH + c * 4 + 1], a1);
        a2 = fmaf(hv, sW[k * HH + c * 4 + 2], a2);
        a3 = fmaf(hv, sW[k * HH + c * 4 + 3], a3);
    }
    reinterpret_cast<float4*>(g_u)[node * 8 + c] = make_float4(a0, a1, a2, a3);
}

// reg_output[g] = (pooled[g]/max(cnt,1)) @ Wr + br
__global__ void k_reg(const float* __restrict__ Wr, const float* __restrict__ br,
                      float* __restrict__ out) {
    int g = blockIdx.x * blockDim.x + threadIdx.x;
    if (g >= GG) return;
    float c = g_cnt[g];
    c = c < 1.f ? 1.f : c;
    float acc = 0.f;
#pragma unroll
    for (int h = 0; h < HH; h++) acc = fmaf(g_pooled[g * HH + h], Wr[h], acc);
    out[g] = acc / c + br[0];
}

// edge_pred[e] = dot(u[src_e], h[dst_e]) + bbil   (8 threads/edge, float4)
__global__ void k_edge(const int* __restrict__ asrc, const int* __restrict__ adst,
                       const float* __restrict__ bbil, float* __restrict__ out) {
    long t = (long)blockIdx.x * blockDim.x + threadIdx.x;
    int e = (int)(t >> 3), lane = (int)(t & 7);
    if (e >= EAA) return;
    float4 a = reinterpret_cast<const float4*>(g_u)[asrc[e] * 8 + lane];
    float4 b = reinterpret_cast<const float4*>(g_h)[adst[e] * 8 + lane];
    float p = a.x * b.x + a.y * b.y + a.z * b.z + a.w * b.w;
#pragma unroll
    for (int off = 4; off; off >>= 1) p += __shfl_down_sync(0xffffffffu, p, off, 8);
    if (lane == 0) out[GG + e] = p + bbil[0];
}

// ---------------- launch ----------------

extern "C" void kernel_launch(void* const* d_in, const int* in_sizes, int n_in,
                              void* d_out, int out_size) {
    const float* x    = (const float*)d_in[0];
    const int*   ei   = (const int*)  d_in[1];
    const int*   eia  = (const int*)  d_in[2];
    const int*   batch= (const int*)  d_in[3];
    const float* W1   = (const float*)d_in[4];
    const float* b1   = (const float*)d_in[5];
    const float* W2   = (const float*)d_in[6];
    const float* b2   = (const float*)d_in[7];
    const float* Wr   = (const float*)d_in[8];
    const float* br   = (const float*)d_in[9];
    const float* Wbil = (const float*)d_in[10];
    const float* bbil = (const float*)d_in[11];
    float* out = (float*)d_out;

    const int* src  = ei;
    const int* dst  = ei + EE;
    const int* asrc = eia;
    const int* adst = eia + EAA;

    const int B = 256;

    // CSR build
    k_zero <<<(NN + B - 1) / B, B>>>();
    k_count<<<(EE / 4 + B - 1) / B, B>>>(dst);
    k_scan <<<SCAN_GRID, SCAN_B>>>();
    k_fill <<<(EE / 4 + B - 1) / B, B>>>(src, dst);

    // layer 1 matmul, then fused gather+relu+layer2 matmul (y1 -> y2)
    k_mm1  <<<(NN * 4 + B - 1) / B, B>>>(x, W1);
    k_gmm  <<<(NN + NODES_PER_BLK - 1) / NODES_PER_BLK, B>>>(b1, W2);

    // fused gather(y2) + epilogue + pooling + bilinear precompute
    k_ghead<<<(NN + NODES_PER_BLK - 1) / NODES_PER_BLK, B>>>(b2, Wbil, batch);

    // heads
    k_reg  <<<(GG + B - 1) / B, B>>>(Wr, br, out);
    k_edge <<<(int)(((long)EAA * 8 + B - 1) / B), B>>>(asrc, adst, bbil, out);
}